// round 12
// baseline (speedup 1.0000x reference)
#include <cuda_runtime.h>
#include <cstdint>
#include <cstddef>

#define T_DIM 1024
#define H_DIM 512
#define B_DIM 64
#define NBLK  144
#define THR   512
#define DYN_SMEM 135168

// ---------------------------------------------------------------------------
// Device-global scratch
// ---------------------------------------------------------------------------
__device__ float g_l[B_DIM * H_DIM * 8];        // l[b][h][k]  (k contiguous)
__device__ float g_f[B_DIM * H_DIM];            // f[b][h] (sigmoided)
__device__ float g_o[B_DIM * H_DIM];            // o[b][h] (sigmoided)
__device__ float g_hT[H_DIM * B_DIM];           // hT[h][b]
__device__ volatile unsigned g_flags[NBLK];
__device__ volatile unsigned g_epoch;

// ---------------------------------------------------------------------------
__device__ __forceinline__ unsigned long long pack2(float v) {
    unsigned long long r;
    asm("mov.b64 %0, {%1, %1};" : "=l"(r) : "f"(v));
    return r;
}
__device__ __forceinline__ unsigned long long fma2(unsigned long long a,
                                                   unsigned long long b,
                                                   unsigned long long c) {
    unsigned long long d;
    asm("fma.rn.f32x2 %0, %1, %2, %3;" : "=l"(d) : "l"(a), "l"(b), "l"(c));
    return d;
}
__device__ __forceinline__ float2 unpack2(unsigned long long v) {
    float2 f;
    asm("mov.b64 {%0, %1}, %2;" : "=f"(f.x), "=f"(f.y) : "l"(v));
    return f;
}

__device__ __forceinline__ float fsig(float x) {
    x = fminf(fmaxf(x, -30.f), 30.f);
    return 1.f / (1.f + __expf(-x));
}
__device__ __forceinline__ float ftanh(float x) {
    x = fminf(fmaxf(x, -15.f), 15.f);
    float e = __expf(2.f * x);
    return (e - 1.f) / (e + 1.f);
}

struct Ptrs { const float* p[28]; };

__device__ __forceinline__ void matInfo(const Ptrs& P, int m,
                                        const float*& W, const float*& bias,
                                        const float*& X, int& C) {
    if (m < 4) {
        C = 8; X = P.p[0];
        W = P.p[8 + 3 * m]; bias = P.p[10 + 3 * m];
    } else if (m < 11) {
        int k = m - 4; C = 3;
        X = P.p[(k == 0) ? 1 : 2];                 // aux input gates: x1 then x2 (faithful quirk)
        W = P.p[20] + (size_t)k * 3 * H_DIM; bias = P.p[22] + (size_t)k * H_DIM;
    } else {
        int k = m - 11; C = 3;
        X = P.p[1 + k];                            // aux candidates: x1..x7
        W = P.p[23] + (size_t)k * 3 * H_DIM; bias = P.p[25] + (size_t)k * H_DIM;
    }
}
__device__ __forceinline__ const float* Uptr(const Ptrs& P, int m) {
    if (m < 4)  return P.p[9 + 3 * m];
    if (m < 11) return P.p[21] + (size_t)(m - 4)  * H_DIM * H_DIM;
    return             P.p[24] + (size_t)(m - 11) * H_DIM * H_DIM;
}

// ---------------------------------------------------------------------------
__global__ void reset_kernel() {
    int i = blockIdx.x * blockDim.x + threadIdx.x;
    int n = gridDim.x * blockDim.x;
    if (i == 0) g_epoch = 0u;
    if (i < NBLK) g_flags[i] = 0u;
    for (int k = i; k < H_DIM * B_DIM; k += n) g_hT[k] = 0.f;
}

// ---------------------------------------------------------------------------
__device__ __forceinline__ void grid_barrier(unsigned target) {
    __syncthreads();
    if (threadIdx.x == 0) {
        __threadfence();
        g_flags[blockIdx.x] = target;
    }
    if (blockIdx.x == 0) {
        if (threadIdx.x < NBLK) {
            while (g_flags[threadIdx.x] < target) __nanosleep(64);
        }
        __syncthreads();
        if (threadIdx.x == 0) {
            __threadfence();
            g_epoch = target;
        }
    }
    if (threadIdx.x == 0) {
        while (g_epoch < target) __nanosleep(64);
        __threadfence();
    }
    __syncthreads();
}

// ---------------------------------------------------------------------------
// Persistent kernel: 144 CTAs x 512 threads.
//
// Phase A: cta = p*16 + jt (9 pairs x 16 j-tiles of 32).
//   thread = kq(4: 128h) x mt(2: mat of pair) x bq(8: 8 batches) x jp(8: 4 j).
//   Per hh: 1 LDS.128 U + 2 LDS.128 h -> 16 FMA2. 4 it-chunks of 32 hh,
//   reg-prefetch double-buffered. 4-way split-K merged via 2-round smem
//   exchange; kq0 does input projection + activation; mt-exchange pairs
//   sig/tanh for l.
// Phase B (cta<128): cta = bt(8) x gt(16: 32 g).
//   thread = kq(4) x bloc(8: batch) x gp(16: 2 g). Per hh: 1 LDS.64 W +
//   2 LDS.128 l -> 8 FMA2. lg zero-init + sum-merge across quarters.
// ---------------------------------------------------------------------------
__global__ void __launch_bounds__(THR, 1)
main_kernel(Ptrs P, float* __restrict__ out) {
    extern __shared__ __align__(16) char dyn[];
    // A: sU [2buf][4kq][2mt][32hh][32j] = 64KB @0
    //    sH [2buf][4kq][32hh][64b]      = 64KB @65536
    //    sX [2mt][64b][8c]              =  4KB @131072
    // B: sL [2buf][4kq][32hh][8bl][8k]  = 64KB @0
    //    sW [2buf][4kq][32hh][32g]      = 32KB @65536
    // exchange: 32KB @0 (buf0 region); A mt-exchange 8KB @65536 (sH buf0)
    float*  sU = (float*)dyn;
    float*  sH = (float*)(dyn + 65536);
    float*  sX = (float*)(dyn + 131072);
    float*  sL = (float*)dyn;
    float*  sW = (float*)(dyn + 65536);
    float4* sEx = (float4*)dyn;
    float*  sEx2 = (float*)(dyn + 65536);

    const int cta = blockIdx.x, tid = threadIdx.x;
    const int kq  = tid >> 7;                 // 0..3
    const int rec = tid & 127;

    // --- phase A ids ---
    const int p   = cta >> 4;
    const int jt  = cta & 15;
    const int jp  = tid & 7;                  // 4 j each
    const int bq  = (tid >> 3) & 7;           // 8 batches each
    const int mt  = (tid >> 6) & 1;
    int mA;
    if      (p == 0) mA = mt ? 2 : 0;
    else if (p == 1) mA = mt ? 3 : 1;
    else             mA = mt ? (11 + p - 2) : (4 + p - 2);
    int m0, m1;                                // pair mats for sX staging
    if      (p == 0) { m0 = 0; m1 = 2; }
    else if (p == 1) { m0 = 1; m1 = 3; }
    else             { m0 = 4 + (p - 2); m1 = 11 + (p - 2); }

    const float *Wm, *bm, *Xm; int Cm;
    matInfo(P, mA, Wm, bm, Xm, Cm);            // this thread's mat (epilogue)
    const float *WA, *bA0, *XA; int Ca;
    const float *WB, *bB0, *XB; int Cb;
    matInfo(P, m0, WA, bA0, XA, Ca);
    matInfo(P, m1, WB, bB0, XB, Cb);
    const float* Um[2] = { Uptr(P, m0) + jt * 32, Uptr(P, m1) + jt * 32 };

    // --- phase B ids ---
    const int bt    = cta >> 4;                // cta<128
    const int gt    = cta & 15;
    const int bloc  = (tid >> 4) & 7;
    const int gp    = tid & 15;
    const int bB_   = bt * 8 + bloc;
    const int g0    = gt * 32 + gp * 2;
    const int g1    = g0 + 1;
    const int kq_own = g0 >> 7;
    const int it_own = (g0 >> 5) & 3;
    const int hl0    = g0 & 31;
    const float* W_a = P.p[26];
    const float  ba0 = P.p[27][g0 & (H_DIM - 1)];
    const float  ba1 = P.p[27][g1 & (H_DIM - 1)];
    float c0 = 0.f, c1 = 0.f;

    float4 uR[4], hR[4];
    float4 lRb[4], wRb[2];

#define LD_A(it) do { \
    _Pragma("unroll") \
    for (int r = 0; r < 4; r++) { int i = tid + r * THR; \
        int kqs = i >> 9, mts = (i >> 8) & 1, hhl = (i >> 3) & 31, f4 = i & 7; \
        uR[r] = __ldg((const float4*)(Um[mts] + (size_t)(kqs * 128 + (it) * 32 + hhl) * H_DIM) + f4); } \
    _Pragma("unroll") \
    for (int r = 0; r < 4; r++) { int i = tid + r * THR; \
        int kqs = i >> 9, hhl = (i >> 4) & 31, f4 = i & 15; \
        hR[r] = __ldcg((const float4*)(g_hT + (kqs * 128 + (it) * 32 + hhl) * B_DIM) + f4); } \
} while (0)
#define ST_A(buf) do { \
    _Pragma("unroll") \
    for (int r = 0; r < 4; r++) { int i = tid + r * THR; \
        int kqs = i >> 9, mts = (i >> 8) & 1, hhl = (i >> 3) & 31, f4 = i & 7; \
        ((float4*)sU)[(((buf) * 4 + kqs) * 2 + mts) * 256 + hhl * 8 + f4] = uR[r]; } \
    _Pragma("unroll") \
    for (int r = 0; r < 4; r++) { int i = tid + r * THR; \
        int kqs = i >> 9, hhl = (i >> 4) & 31, f4 = i & 15; \
        ((float4*)sH)[((buf) * 4 + kqs) * 512 + hhl * 16 + f4] = hR[r]; } \
} while (0)
#define LD_B(it) do { \
    _Pragma("unroll") \
    for (int r = 0; r < 4; r++) { int i = tid + r * THR; \
        int kqs = i >> 9, rr = i & 511, hhl = rr >> 4, bl = (rr >> 1) & 7, k4 = i & 1; \
        lRb[r] = __ldcg((const float4*)(g_l + ((size_t)(bt * 8 + bl) * H_DIM \
                        + kqs * 128 + (it) * 32 + hhl) * 8) + k4); } \
    _Pragma("unroll") \
    for (int r = 0; r < 2; r++) { int i = tid + r * THR; \
        int kqs = i >> 8, hhl = (i >> 3) & 31, f4 = i & 7; \
        wRb[r] = __ldg((const float4*)(W_a + (size_t)(kqs * 128 + (it) * 32 + hhl) * H_DIM \
                        + gt * 32) + f4); } \
} while (0)
#define ST_B(buf) do { \
    _Pragma("unroll") \
    for (int r = 0; r < 4; r++) { int i = tid + r * THR; \
        int kqs = i >> 9, rr = i & 511, hhl = rr >> 4, bl = (rr >> 1) & 7, k4 = i & 1; \
        ((float4*)sL)[((buf) * 4 + kqs) * 512 + (hhl * 8 + bl) * 2 + k4] = lRb[r]; } \
    _Pragma("unroll") \
    for (int r = 0; r < 2; r++) { int i = tid + r * THR; \
        int kqs = i >> 8, hhl = (i >> 3) & 31, f4 = i & 7; \
        ((float4*)sW)[((buf) * 4 + kqs) * 256 + hhl * 8 + f4] = wRb[r]; } \
} while (0)

    for (int t = 0; t < T_DIM; t++) {
        // =============== Phase A ===============
        unsigned long long acc[16];
        #pragma unroll
        for (int i = 0; i < 16; i++) acc[i] = 0ull;

        LD_A(0);
        for (int i = tid; i < 64 * Ca; i += THR) {
            int b = i / Ca, c = i - b * Ca;
            sX[b * 8 + c] = XA[((size_t)b * Ca + c) * T_DIM + t];
        }
        for (int i = tid; i < 64 * Cb; i += THR) {
            int b = i / Cb, c = i - b * Cb;
            sX[512 + b * 8 + c] = XB[((size_t)b * Cb + c) * T_DIM + t];
        }
        ST_A(0);
        __syncthreads();

        #pragma unroll 1
        for (int it = 0; it < 4; it++) {
            if (it < 3) LD_A(it + 1);
            const int buf = it & 1;
            const float* Uf = sU + ((buf * 4 + kq) * 2 + mt) * 1024;
            const float* Hf = sH + (buf * 4 + kq) * 2048;
            #pragma unroll 4
            for (int hh = 0; hh < 32; hh++) {
                float4 u4 = *(const float4*)(Uf + hh * 32 + jp * 4);
                ulonglong2 hA = *(const ulonglong2*)(Hf + hh * 64 + bq * 8);
                ulonglong2 hB = *(const ulonglong2*)(Hf + hh * 64 + bq * 8 + 4);
                unsigned long long up;
                up = pack2(u4.x);
                acc[0]  = fma2(hA.x, up, acc[0]);  acc[1]  = fma2(hA.y, up, acc[1]);
                acc[2]  = fma2(hB.x, up, acc[2]);  acc[3]  = fma2(hB.y, up, acc[3]);
                up = pack2(u4.y);
                acc[4]  = fma2(hA.x, up, acc[4]);  acc[5]  = fma2(hA.y, up, acc[5]);
                acc[6]  = fma2(hB.x, up, acc[6]);  acc[7]  = fma2(hB.y, up, acc[7]);
                up = pack2(u4.z);
                acc[8]  = fma2(hA.x, up, acc[8]);  acc[9]  = fma2(hA.y, up, acc[9]);
                acc[10] = fma2(hB.x, up, acc[10]); acc[11] = fma2(hB.y, up, acc[11]);
                up = pack2(u4.w);
                acc[12] = fma2(hA.x, up, acc[12]); acc[13] = fma2(hA.y, up, acc[13]);
                acc[14] = fma2(hB.x, up, acc[14]); acc[15] = fma2(hB.y, up, acc[15]);
            }
            if (it < 3) { __syncthreads(); ST_A((it + 1) & 1); __syncthreads(); }
        }

        // unpack to floats: z[(jj*4+bb)*2 + s]; j = jt*32+jp*4+jj, b = bq*8+bb*2+s
        float z[32];
        #pragma unroll
        for (int i = 0; i < 16; i++) {
            float2 q = unpack2(acc[i]);
            z[2 * i] = q.x; z[2 * i + 1] = q.y;
        }

        // 4-way split-K reduce (2 rounds); exchange over sU buf0 (free after it2)
        if (kq == 1) { float4* d = sEx + rec * 8;
            #pragma unroll
            for (int q = 0; q < 8; q++) d[q] = make_float4(z[4*q], z[4*q+1], z[4*q+2], z[4*q+3]); }
        if (kq == 3) { float4* d = sEx + (128 + rec) * 8;
            #pragma unroll
            for (int q = 0; q < 8; q++) d[q] = make_float4(z[4*q], z[4*q+1], z[4*q+2], z[4*q+3]); }
        __syncthreads();
        if (kq == 0) { const float* s = (const float*)(sEx + rec * 8);
            #pragma unroll
            for (int i = 0; i < 32; i++) z[i] += s[i]; }
        if (kq == 2) { const float* s = (const float*)(sEx + (128 + rec) * 8);
            #pragma unroll
            for (int i = 0; i < 32; i++) z[i] += s[i];
            float4* d = sEx + (128 + rec) * 8;
            #pragma unroll
            for (int q = 0; q < 8; q++) d[q] = make_float4(z[4*q], z[4*q+1], z[4*q+2], z[4*q+3]); }
        __syncthreads();
        if (kq == 0) {
            const float* s = (const float*)(sEx + (128 + rec) * 8);
            #pragma unroll
            for (int i = 0; i < 32; i++) z[i] += s[i];
            // input projection + bias (this thread's mat mA)
            const float* sxm = sX + mt * 512;
            #pragma unroll
            for (int jj = 0; jj < 4; jj++) {
                float bj = __ldg(bm + jt * 32 + jp * 4 + jj);
                #pragma unroll
                for (int b8 = 0; b8 < 8; b8++) z[(jj * 4 + (b8 >> 1)) * 2 + (b8 & 1)] += bj;
            }
            for (int c = 0; c < Cm; c++) {
                float xv[8];
                #pragma unroll
                for (int b8 = 0; b8 < 8; b8++) xv[b8] = sxm[(bq * 8 + b8) * 8 + c];
                #pragma unroll
                for (int jj = 0; jj < 4; jj++) {
                    float wv = __ldg(Wm + (size_t)c * H_DIM + jt * 32 + jp * 4 + jj);
                    #pragma unroll
                    for (int b8 = 0; b8 < 8; b8++)
                        z[(jj * 4 + (b8 >> 1)) * 2 + (b8 & 1)] = fmaf(wv, xv[b8], z[(jj * 4 + (b8 >> 1)) * 2 + (b8 & 1)]);
                }
            }
            if (p == 1) {
                float* dst = mt ? g_o : g_f;
                #pragma unroll
                for (int jj = 0; jj < 4; jj++)
                    #pragma unroll
                    for (int b8 = 0; b8 < 8; b8++)
                        dst[(bq * 8 + b8) * H_DIM + jt * 32 + jp * 4 + jj] =
                            fsig(z[(jj * 4 + (b8 >> 1)) * 2 + (b8 & 1)]);
            } else if (mt == 1) {
                float* d = sEx2 + (bq * 8 + jp) * 32;
                #pragma unroll
                for (int i = 0; i < 32; i++) d[i] = z[i];
            }
        }
        __syncthreads();
        if (kq == 0 && mt == 0 && p != 1) {
            const float* zc = sEx2 + (bq * 8 + jp) * 32;
            int k = (p == 0) ? 0 : (p - 1);
            #pragma unroll
            for (int jj = 0; jj < 4; jj++)
                #pragma unroll
                for (int b8 = 0; b8 < 8; b8++) {
                    int idx = (jj * 4 + (b8 >> 1)) * 2 + (b8 & 1);
                    g_l[((size_t)(bq * 8 + b8) * H_DIM + jt * 32 + jp * 4 + jj) * 8 + k] =
                        fsig(z[idx]) * ftanh(zc[idx]);
                }
        }

        grid_barrier(2 * t + 1);

        // =============== Phase B ===============
        if (cta < 128) {
            unsigned long long accb[8];
            #pragma unroll
            for (int i = 0; i < 8; i++) accb[i] = 0ull;
            float lg[16];
            #pragma unroll
            for (int i = 0; i < 16; i++) lg[i] = 0.f;

            LD_B(0); ST_B(0); __syncthreads();

            #pragma unroll 1
            for (int it = 0; it < 4; it++) {
                if (it < 3) LD_B(it + 1);
                const int buf = it & 1;
                const float* Wf = sW + (buf * 4 + kq) * 1024;
                const float* Lf = sL + (buf * 4 + kq) * 2048;
                if (kq == kq_own && it == it_own) {
                    const ulonglong2* Lv = (const ulonglong2*)Lf;
                    ulonglong2 v0 = Lv[hl0 * 16 + bloc * 2];
                    ulonglong2 v1 = Lv[hl0 * 16 + bloc * 2 + 1];
                    ulonglong2 v2 = Lv[(hl0 + 1) * 16 + bloc * 2];
                    ulonglong2 v3 = Lv[(hl0 + 1) * 16 + bloc * 2 + 1];
                    float2 q;
                    q = unpack2(v0.x); lg[0] = q.x; lg[1] = q.y;
                    q = unpack2(v0.y); lg[2] = q.x; lg[3] = q.y;
                    q = unpack2(v1.x); lg[4] = q.x; lg[5] = q.y;
                    q = unpack2(v1.y); lg[6] = q.x; lg[7] = q.y;
                    q = unpack2(v2.x); lg[8] = q.x; lg[9] = q.y;
                    q = unpack2(v2.y); lg[10] = q.x; lg[11] = q.y;
                    q = unpack2(v3.x); lg[12] = q.x; lg[13] = q.y;
                    q = unpack2(v3.y); lg[14] = q.x; lg[15] = q.y;
                }
                #pragma unroll 4
                for (int hh = 0; hh < 32; hh++) {
                    float2 wv = *(const float2*)(Wf + hh * 32 + gp * 2);
                    const ulonglong2* Lv = (const ulonglong2*)Lf;
                    ulonglong2 v0 = Lv[hh * 16 + bloc * 2];
                    ulonglong2 v1 = Lv[hh * 16 + bloc * 2 + 1];
                    unsigned long long w0 = pack2(wv.x);
                    unsigned long long w1 = pack2(wv.y);
                    accb[0] = fma2(v0.x, w0, accb[0]);
                    accb[1] = fma2(v0.y, w0, accb[1]);
                    accb[2] = fma2(v1.x, w0, accb[2]);
                    accb[3] = fma2(v1.y, w0, accb[3]);
                    accb[4] = fma2(v0.x, w1, accb[4]);
                    accb[5] = fma2(v0.y, w1, accb[5]);
                    accb[6] = fma2(v1.x, w1, accb[6]);
                    accb[7] = fma2(v1.y, w1, accb[7]);
                }
                if (it < 3) { __syncthreads(); ST_B((it + 1) & 1); __syncthreads(); }
            }

            // pack a(16) + lg(16) into 32 floats; 2-round reduce (lg sum-merges)
            float zb[32];
            #pragma unroll
            for (int i = 0; i < 8; i++) {
                float2 q = unpack2(accb[i]);
                zb[2 * i] = q.x; zb[2 * i + 1] = q.y;
            }
            #pragma unroll
            for (int i = 0; i < 16; i++) zb[16 + i] = lg[i];

            if (kq == 1) { float4* d = sEx + rec * 8;
                #pragma unroll
                for (int q = 0; q < 8; q++) d[q] = make_float4(zb[4*q], zb[4*q+1], zb[4*q+2], zb[4*q+3]); }
            if (kq == 3) { float4* d = sEx + (128 + rec) * 8;
                #pragma unroll
                for (int q = 0; q < 8; q++) d[q] = make_float4(zb[4*q], zb[4*q+1], zb[4*q+2], zb[4*q+3]); }
            __syncthreads();
            if (kq == 0) { const float* s = (const float*)(sEx + rec * 8);
                #pragma unroll
                for (int i = 0; i < 32; i++) zb[i] += s[i]; }
            if (kq == 2) { const float* s = (const float*)(sEx + (128 + rec) * 8);
                #pragma unroll
                for (int i = 0; i < 32; i++) zb[i] += s[i];
                float4* d = sEx + (128 + rec) * 8;
                #pragma unroll
                for (int q = 0; q < 8; q++) d[q] = make_float4(zb[4*q], zb[4*q+1], zb[4*q+2], zb[4*q+3]); }
            __syncthreads();
            if (kq == 0) {
                const float* s = (const float*)(sEx + (128 + rec) * 8);
                #pragma unroll
                for (int i = 0; i < 32; i++) zb[i] += s[i];
                // zb[0..7] = a(g0,k), zb[8..15] = a(g1,k)
                // zb[16..23] = l(g0,k), zb[24..31] = l(g1,k)
                float u0[8], u1[8], mx0 = -1e30f, mx1 = -1e30f;
                #pragma unroll
                for (int k = 0; k < 8; k++) {
                    u0[k] = ftanh(fmaf(zb[k], c0, ba0));
                    u1[k] = ftanh(fmaf(zb[8 + k], c1, ba1));
                    mx0 = fmaxf(mx0, u0[k]);
                    mx1 = fmaxf(mx1, u1[k]);
                }
                float es0 = 0.f, L0 = 0.f, es1 = 0.f, L1 = 0.f;
                #pragma unroll
                for (int k = 0; k < 8; k++) {
                    float e0 = __expf(u0[k] - mx0);
                    float e1 = __expf(u1[k] - mx1);
                    es0 += e0; L0 += e0 * zb[16 + k];
                    es1 += e1; L1 += e1 * zb[24 + k];
                }
                L0 /= es0; L1 /= es1;
                int idx = bB_ * H_DIM + g0;
                float2 fv = __ldcg((const float2*)&g_f[idx]);
                float2 ov = __ldcg((const float2*)&g_o[idx]);
                c0 = fmaf(fv.x, c0, L0);
                c1 = fmaf(fv.y, c1, L1);
                float hn0 = ov.x * ftanh(c0);
                float hn1 = ov.y * ftanh(c1);
                g_hT[g0 * B_DIM + bB_] = hn0;
                g_hT[g1 * B_DIM + bB_] = hn1;
                *(float2*)&out[(size_t)B_DIM * H_DIM + ((size_t)bB_ * T_DIM + t) * H_DIM + g0] =
                    make_float2(hn0, hn1);
                if (t == T_DIM - 1)
                    *(float2*)&out[bB_ * H_DIM + g0] = make_float2(hn0, hn1);
            }
        }

        grid_barrier(2 * t + 2);
    }
#undef LD_A
#undef ST_A
#undef LD_B
#undef ST_B
}

// ---------------------------------------------------------------------------
extern "C" void kernel_launch(void* const* d_in, const int* in_sizes, int n_in,
                              void* d_out, int out_size) {
    (void)in_sizes; (void)n_in; (void)out_size;
    Ptrs P;
    for (int i = 0; i < 28; i++) P.p[i] = (const float*)d_in[i];

    cudaFuncSetAttribute(main_kernel,
                         cudaFuncAttributeMaxDynamicSharedMemorySize, DYN_SMEM);

    reset_kernel<<<64, 256>>>();
    main_kernel<<<NBLK, THR, DYN_SMEM>>>(P, (float*)d_out);
}

// round 13
// speedup vs baseline: 1.1586x; 1.1586x over previous
#include <cuda_runtime.h>
#include <cstdint>
#include <cstddef>

#define T_DIM 1024
#define H_DIM 512
#define B_DIM 64
#define NBLK  144
#define THR   512
#define DYN_SMEM 135168

// ---------------------------------------------------------------------------
// Device-global scratch
// ---------------------------------------------------------------------------
__device__ float g_l[B_DIM * H_DIM * 8];        // l[b][h][k]  (k contiguous)
__device__ float g_f[B_DIM * H_DIM];            // f[b][h] (sigmoided)
__device__ float g_o[B_DIM * H_DIM];            // o[b][h] (sigmoided)
__device__ float g_hT[H_DIM * B_DIM];           // hT[h][b]
__device__ volatile unsigned g_flags[NBLK];
__device__ volatile unsigned g_epoch;

// ---------------------------------------------------------------------------
__device__ __forceinline__ unsigned long long pack2(float v) {
    unsigned long long r;
    asm("mov.b64 %0, {%1, %1};" : "=l"(r) : "f"(v));
    return r;
}
__device__ __forceinline__ unsigned long long fma2(unsigned long long a,
                                                   unsigned long long b,
                                                   unsigned long long c) {
    unsigned long long d;
    asm("fma.rn.f32x2 %0, %1, %2, %3;" : "=l"(d) : "l"(a), "l"(b), "l"(c));
    return d;
}
__device__ __forceinline__ unsigned long long add2(unsigned long long a,
                                                   unsigned long long b) {
    unsigned long long d;
    asm("add.rn.f32x2 %0, %1, %2;" : "=l"(d) : "l"(a), "l"(b));
    return d;
}
__device__ __forceinline__ float2 unpack2(unsigned long long v) {
    float2 f;
    asm("mov.b64 {%0, %1}, %2;" : "=f"(f.x), "=f"(f.y) : "l"(v));
    return f;
}

__device__ __forceinline__ void cpa_cg(unsigned dst, const float* src) {
    asm volatile("cp.async.cg.shared.global [%0], [%1], 16;" :: "r"(dst), "l"(src));
}
__device__ __forceinline__ void cpa_ca(unsigned dst, const float* src) {
    asm volatile("cp.async.ca.shared.global [%0], [%1], 16;" :: "r"(dst), "l"(src));
}
#define CP_COMMIT() asm volatile("cp.async.commit_group;" ::: "memory")
#define CP_WAIT1()  asm volatile("cp.async.wait_group 1;" ::: "memory")
#define CP_WAIT0()  asm volatile("cp.async.wait_group 0;" ::: "memory")

__device__ __forceinline__ float fsig(float x) {
    x = fminf(fmaxf(x, -30.f), 30.f);
    return 1.f / (1.f + __expf(-x));
}
__device__ __forceinline__ float ftanh(float x) {
    x = fminf(fmaxf(x, -15.f), 15.f);
    float e = __expf(2.f * x);
    return (e - 1.f) / (e + 1.f);
}

struct Ptrs { const float* p[28]; };

__device__ __forceinline__ void matInfo(const Ptrs& P, int m,
                                        const float*& W, const float*& bias,
                                        const float*& X, int& C) {
    if (m < 4) {
        C = 8; X = P.p[0];
        W = P.p[8 + 3 * m]; bias = P.p[10 + 3 * m];
    } else if (m < 11) {
        int k = m - 4; C = 3;
        X = P.p[(k == 0) ? 1 : 2];                 // aux input gates: x1 then x2 (faithful quirk)
        W = P.p[20] + (size_t)k * 3 * H_DIM; bias = P.p[22] + (size_t)k * H_DIM;
    } else {
        int k = m - 11; C = 3;
        X = P.p[1 + k];                            // aux candidates: x1..x7
        W = P.p[23] + (size_t)k * 3 * H_DIM; bias = P.p[25] + (size_t)k * H_DIM;
    }
}
__device__ __forceinline__ const float* Uptr(const Ptrs& P, int m) {
    if (m < 4)  return P.p[9 + 3 * m];
    if (m < 11) return P.p[21] + (size_t)(m - 4)  * H_DIM * H_DIM;
    return             P.p[24] + (size_t)(m - 11) * H_DIM * H_DIM;
}

// ---------------------------------------------------------------------------
__global__ void reset_kernel() {
    int i = blockIdx.x * blockDim.x + threadIdx.x;
    int n = gridDim.x * blockDim.x;
    if (i == 0) g_epoch = 0u;
    if (i < NBLK) g_flags[i] = 0u;
    for (int k = i; k < H_DIM * B_DIM; k += n) g_hT[k] = 0.f;
}

// ---------------------------------------------------------------------------
__device__ __forceinline__ void grid_barrier(unsigned target) {
    __syncthreads();
    if (threadIdx.x == 0) {
        __threadfence();
        g_flags[blockIdx.x] = target;
    }
    if (blockIdx.x == 0) {
        if (threadIdx.x < NBLK) {
            while (g_flags[threadIdx.x] < target) __nanosleep(64);
        }
        __syncthreads();
        if (threadIdx.x == 0) {
            __threadfence();
            g_epoch = target;
        }
    }
    if (threadIdx.x == 0) {
        while (g_epoch < target) __nanosleep(64);
        __threadfence();
    }
    __syncthreads();
}

// ---------------------------------------------------------------------------
// Persistent kernel: 144 CTAs x 512 threads, 132KB dynamic smem.
// Phase A: cta = p*16 + jt; thread = kq(4) x mt(2) x bq(8) x jp(8): 4j x 8b.
//   cp.async double-buffered staging; per warp-hh: 3 LDS -> 16 FMA2.
//   Single-round packed split-K exchange (conflict-free [slot][rec] layout).
// Phase B (cta<128): cta = bt(8) x gt(16); thread = kq(4) x bloc(8) x gp(16).
// ---------------------------------------------------------------------------
__global__ void __launch_bounds__(THR, 1)
main_kernel(Ptrs P, float* __restrict__ out) {
    extern __shared__ __align__(16) char dyn[];
    // A: sU [2buf][4kq][2mt][32hh][32j] = 64KB @0
    //    sH [2buf][4kq][32hh][64b]      = 64KB @65536
    //    sX [2mt][64b][8c]              =  4KB @131072
    // B: sL [2buf][4kq][32hh][8bl][8k]  = 64KB @0
    //    sW [2buf][4kq][32hh][32g]      = 32KB @65536
    // Exchange (after last compute, which uses buf1 only):
    //    E1 @0 (16KB), E2 @16384 (16KB), E3 @65536 (16KB), mtEx @81920 (8KB)
    float*  sU = (float*)dyn;
    float*  sH = (float*)(dyn + 65536);
    float*  sX = (float*)(dyn + 131072);
    float*  sW = (float*)(dyn + 65536);
    float*  sL = (float*)dyn;
    float4* mtEx = (float4*)(dyn + 81920);
    const unsigned smem_u32 = (unsigned)__cvta_generic_to_shared(dyn);

    const int cta = blockIdx.x, tid = threadIdx.x;
    const int kq  = tid >> 7;                 // 0..3
    const int rec = tid & 127;

    // --- phase A ids ---
    const int p   = cta >> 4;
    const int jt  = cta & 15;
    const int jp  = tid & 7;                  // 4 j each
    const int bq  = (tid >> 3) & 7;           // 8 batches each
    const int mt  = (tid >> 6) & 1;
    int mA;
    if      (p == 0) mA = mt ? 2 : 0;
    else if (p == 1) mA = mt ? 3 : 1;
    else             mA = mt ? (11 + p - 2) : (4 + p - 2);
    int m0, m1;
    if      (p == 0) { m0 = 0; m1 = 2; }
    else if (p == 1) { m0 = 1; m1 = 3; }
    else             { m0 = 4 + (p - 2); m1 = 11 + (p - 2); }

    const float *Wm, *bm, *Xm; int Cm;
    matInfo(P, mA, Wm, bm, Xm, Cm);
    const float *WA, *bA0, *XA; int Ca;
    const float *WB, *bB0, *XB; int Cb;
    matInfo(P, m0, WA, bA0, XA, Ca);
    matInfo(P, m1, WB, bB0, XB, Cb);
    const float* Um[2] = { Uptr(P, m0) + jt * 32, Uptr(P, m1) + jt * 32 };

    // --- phase B ids ---
    const int bt    = cta >> 4;                // cta<128
    const int gt    = cta & 15;
    const int bloc  = (tid >> 4) & 7;
    const int gp    = tid & 15;
    const int bB_   = bt * 8 + bloc;
    const int g0    = gt * 32 + gp * 2;
    const int g1    = g0 + 1;
    const int kq_own = g0 >> 7;
    const int it_own = (g0 >> 5) & 3;
    const int hl0    = g0 & 31;
    const float* W_a = P.p[26];
    const float  ba0 = P.p[27][g0 & (H_DIM - 1)];
    const float  ba1 = P.p[27][g1 & (H_DIM - 1)];
    float c0 = 0.f, c1 = 0.f;

#define PF_A(it, bufb) do { \
    _Pragma("unroll") \
    for (int r = 0; r < 4; r++) { int i = tid + r * THR; \
        int kqs = i >> 9, mts = (i >> 8) & 1, hhl = (i >> 3) & 31, f4 = i & 7; \
        cpa_ca(smem_u32 + (((((bufb) * 4 + kqs) * 2 + mts) * 256 + hhl * 8 + f4) << 4), \
               Um[mts] + (size_t)(kqs * 128 + (it) * 32 + hhl) * H_DIM + f4 * 4); } \
    _Pragma("unroll") \
    for (int r = 0; r < 4; r++) { int i = tid + r * THR; \
        int kqs = i >> 9, hhl = (i >> 4) & 31, f4 = i & 15; \
        cpa_cg(smem_u32 + 65536 + (((((bufb) * 4 + kqs) * 512) + hhl * 16 + f4) << 4), \
               g_hT + (kqs * 128 + (it) * 32 + hhl) * B_DIM + f4 * 4); } \
    CP_COMMIT(); \
} while (0)
#define PF_B(it, bufb) do { \
    _Pragma("unroll") \
    for (int r = 0; r < 4; r++) { int i = tid + r * THR; \
        int kqs = i >> 9, rr = i & 511, hhl = rr >> 4, bl = (rr >> 1) & 7, k4 = i & 1; \
        cpa_cg(smem_u32 + (((((bufb) * 4 + kqs) * 512) + (hhl * 8 + bl) * 2 + k4) << 4), \
               g_l + ((size_t)(bt * 8 + bl) * H_DIM + kqs * 128 + (it) * 32 + hhl) * 8 + k4 * 4); } \
    _Pragma("unroll") \
    for (int r = 0; r < 2; r++) { int i = tid + r * THR; \
        int kqs = i >> 8, hhl = (i >> 3) & 31, f4 = i & 7; \
        cpa_ca(smem_u32 + 65536 + (((((bufb) * 4 + kqs) * 256) + hhl * 8 + f4) << 4), \
               W_a + (size_t)(kqs * 128 + (it) * 32 + hhl) * H_DIM + gt * 32 + f4 * 4); } \
    CP_COMMIT(); \
} while (0)

    for (int t = 0; t < T_DIM; t++) {
        // =============== Phase A ===============
        unsigned long long acc[16];
        #pragma unroll
        for (int i = 0; i < 16; i++) acc[i] = 0ull;

        PF_A(0, 0);
        PF_A(1, 1);
        for (int i = tid; i < 64 * Ca; i += THR) {
            int b = i / Ca, c = i - b * Ca;
            sX[b * 8 + c] = XA[((size_t)b * Ca + c) * T_DIM + t];
        }
        for (int i = tid; i < 64 * Cb; i += THR) {
            int b = i / Cb, c = i - b * Cb;
            sX[512 + b * 8 + c] = XB[((size_t)b * Cb + c) * T_DIM + t];
        }

        #pragma unroll 1
        for (int it = 0; it < 4; it++) {
            if (it == 3) CP_WAIT0(); else CP_WAIT1();
            __syncthreads();
            const int buf = it & 1;
            const float* Uf = sU + ((buf * 4 + kq) * 2 + mt) * 1024;
            const float* Hf = sH + (buf * 4 + kq) * 2048;
            #pragma unroll 4
            for (int hh = 0; hh < 32; hh++) {
                float4 u4 = *(const float4*)(Uf + hh * 32 + jp * 4);
                ulonglong2 hA = *(const ulonglong2*)(Hf + hh * 64 + bq * 8);
                ulonglong2 hB = *(const ulonglong2*)(Hf + hh * 64 + bq * 8 + 4);
                unsigned long long up;
                up = pack2(u4.x);
                acc[0]  = fma2(hA.x, up, acc[0]);  acc[1]  = fma2(hA.y, up, acc[1]);
                acc[2]  = fma2(hB.x, up, acc[2]);  acc[3]  = fma2(hB.y, up, acc[3]);
                up = pack2(u4.y);
                acc[4]  = fma2(hA.x, up, acc[4]);  acc[5]  = fma2(hA.y, up, acc[5]);
                acc[6]  = fma2(hB.x, up, acc[6]);  acc[7]  = fma2(hB.y, up, acc[7]);
                up = pack2(u4.z);
                acc[8]  = fma2(hA.x, up, acc[8]);  acc[9]  = fma2(hA.y, up, acc[9]);
                acc[10] = fma2(hB.x, up, acc[10]); acc[11] = fma2(hB.y, up, acc[11]);
                up = pack2(u4.w);
                acc[12] = fma2(hA.x, up, acc[12]); acc[13] = fma2(hA.y, up, acc[13]);
                acc[14] = fma2(hB.x, up, acc[14]); acc[15] = fma2(hB.y, up, acc[15]);
            }
            __syncthreads();
            if (it == 0) PF_A(2, 0);
            else if (it == 1) PF_A(3, 1);
        }

        // single-round packed split-K exchange ([slot][rec]: conflict-free)
        if (kq != 0) {
            ulonglong2* reg = (kq == 1) ? (ulonglong2*)dyn
                            : (kq == 2) ? (ulonglong2*)(dyn + 16384)
                                        : (ulonglong2*)(dyn + 65536);
            #pragma unroll
            for (int q = 0; q < 8; q++) {
                ulonglong2 v; v.x = acc[2 * q]; v.y = acc[2 * q + 1];
                reg[q * 128 + rec] = v;
            }
        }
        __syncthreads();
        if (kq == 0) {
            const ulonglong2* R1 = (const ulonglong2*)dyn;
            const ulonglong2* R2 = (const ulonglong2*)(dyn + 16384);
            const ulonglong2* R3 = (const ulonglong2*)(dyn + 65536);
            #pragma unroll
            for (int q = 0; q < 8; q++) {
                ulonglong2 v1 = R1[q * 128 + rec];
                ulonglong2 v2 = R2[q * 128 + rec];
                ulonglong2 v3 = R3[q * 128 + rec];
                acc[2 * q]     = add2(add2(acc[2 * q], v1.x), add2(v2.x, v3.x));
                acc[2 * q + 1] = add2(add2(acc[2 * q + 1], v1.y), add2(v2.y, v3.y));
            }
            float z[32];
            #pragma unroll
            for (int i = 0; i < 16; i++) {
                float2 q2 = unpack2(acc[i]);
                z[2 * i] = q2.x; z[2 * i + 1] = q2.y;
            }
            // input projection + bias (this thread's mat mA)
            const float* sxm = sX + mt * 512;
            #pragma unroll
            for (int jj = 0; jj < 4; jj++) {
                float bj = __ldg(bm + jt * 32 + jp * 4 + jj);
                #pragma unroll
                for (int b8 = 0; b8 < 8; b8++) z[(jj * 4 + (b8 >> 1)) * 2 + (b8 & 1)] += bj;
            }
            for (int c = 0; c < Cm; c++) {
                float xv[8];
                #pragma unroll
                for (int b8 = 0; b8 < 8; b8++) xv[b8] = sxm[(bq * 8 + b8) * 8 + c];
                #pragma unroll
                for (int jj = 0; jj < 4; jj++) {
                    float wv = __ldg(Wm + (size_t)c * H_DIM + jt * 32 + jp * 4 + jj);
                    #pragma unroll
                    for (int b8 = 0; b8 < 8; b8++)
                        z[(jj * 4 + (b8 >> 1)) * 2 + (b8 & 1)] =
                            fmaf(wv, xv[b8], z[(jj * 4 + (b8 >> 1)) * 2 + (b8 & 1)]);
                }
            }
            if (p == 1) {
                float* dst = mt ? g_o : g_f;
                #pragma unroll
                for (int jj = 0; jj < 4; jj++)
                    #pragma unroll
                    for (int b8 = 0; b8 < 8; b8++)
                        dst[(bq * 8 + b8) * H_DIM + jt * 32 + jp * 4 + jj] =
                            fsig(z[(jj * 4 + (b8 >> 1)) * 2 + (b8 & 1)]);
            } else if (mt == 1) {
                int idx = bq * 8 + jp;
                #pragma unroll
                for (int q4 = 0; q4 < 8; q4++)
                    mtEx[q4 * 64 + idx] =
                        make_float4(z[4 * q4], z[4 * q4 + 1], z[4 * q4 + 2], z[4 * q4 + 3]);
            }
            __syncthreads();
            if (mt == 0 && p != 1) {
                int idx = bq * 8 + jp;
                float zc[32];
                #pragma unroll
                for (int q4 = 0; q4 < 8; q4++) {
                    float4 v = mtEx[q4 * 64 + idx];
                    zc[4 * q4] = v.x; zc[4 * q4 + 1] = v.y;
                    zc[4 * q4 + 2] = v.z; zc[4 * q4 + 3] = v.w;
                }
                int k = (p == 0) ? 0 : (p - 1);
                #pragma unroll
                for (int jj = 0; jj < 4; jj++)
                    #pragma unroll
                    for (int b8 = 0; b8 < 8; b8++) {
                        int idz = (jj * 4 + (b8 >> 1)) * 2 + (b8 & 1);
                        g_l[((size_t)(bq * 8 + b8) * H_DIM + jt * 32 + jp * 4 + jj) * 8 + k] =
                            fsig(z[idz]) * ftanh(zc[idz]);
                    }
            }
        } else {
            __syncthreads();
        }

        grid_barrier(2 * t + 1);

        // =============== Phase B ===============
        if (cta < 128) {
            unsigned long long accb[8];
            #pragma unroll
            for (int i = 0; i < 8; i++) accb[i] = 0ull;
            float lg[16];
            #pragma unroll
            for (int i = 0; i < 16; i++) lg[i] = 0.f;

            PF_B(0, 0);
            PF_B(1, 1);

            #pragma unroll 1
            for (int it = 0; it < 4; it++) {
                if (it == 3) CP_WAIT0(); else CP_WAIT1();
                __syncthreads();
                const int buf = it & 1;
                const float* Wf = sW + (buf * 4 + kq) * 1024;
                const float* Lf = sL + (buf * 4 + kq) * 2048;
                if (kq == kq_own && it == it_own) {
                    const ulonglong2* Lv = (const ulonglong2*)Lf;
                    ulonglong2 v0 = Lv[hl0 * 16 + bloc * 2];
                    ulonglong2 v1 = Lv[hl0 * 16 + bloc * 2 + 1];
                    ulonglong2 v2 = Lv[(hl0 + 1) * 16 + bloc * 2];
                    ulonglong2 v3 = Lv[(hl0 + 1) * 16 + bloc * 2 + 1];
                    float2 q2;
                    q2 = unpack2(v0.x); lg[0] = q2.x; lg[1] = q2.y;
                    q2 = unpack2(v0.y); lg[2] = q2.x; lg[3] = q2.y;
                    q2 = unpack2(v1.x); lg[4] = q2.x; lg[5] = q2.y;
                    q2 = unpack2(v1.y); lg[6] = q2.x; lg[7] = q2.y;
                    q2 = unpack2(v2.x); lg[8] = q2.x; lg[9] = q2.y;
                    q2 = unpack2(v2.y); lg[10] = q2.x; lg[11] = q2.y;
                    q2 = unpack2(v3.x); lg[12] = q2.x; lg[13] = q2.y;
                    q2 = unpack2(v3.y); lg[14] = q2.x; lg[15] = q2.y;
                }
                #pragma unroll 4
                for (int hh = 0; hh < 32; hh++) {
                    float2 wv = *(const float2*)(Wf + hh * 32 + gp * 2);
                    const ulonglong2* Lv = (const ulonglong2*)Lf;
                    ulonglong2 v0 = Lv[hh * 16 + bloc * 2];
                    ulonglong2 v1 = Lv[hh * 16 + bloc * 2 + 1];
                    unsigned long long w0 = pack2(wv.x);
                    unsigned long long w1 = pack2(wv.y);
                    accb[0] = fma2(v0.x, w0, accb[0]);
                    accb[1] = fma2(v0.y, w0, accb[1]);
                    accb[2] = fma2(v1.x, w0, accb[2]);
                    accb[3] = fma2(v1.y, w0, accb[3]);
                    accb[4] = fma2(v0.x, w1, accb[4]);
                    accb[5] = fma2(v0.y, w1, accb[5]);
                    accb[6] = fma2(v1.x, w1, accb[6]);
                    accb[7] = fma2(v1.y, w1, accb[7]);
                }
                __syncthreads();
                if (it == 0) PF_B(2, 0);
                else if (it == 1) PF_B(3, 1);
            }

            // single-round packed exchange (a via add2; lg sum-merges, zero-init)
            if (kq != 0) {
                char* reg = (kq == 1) ? dyn : (kq == 2) ? (dyn + 16384) : (dyn + 65536);
                ulonglong2* r2 = (ulonglong2*)reg;
                float4* rf = (float4*)reg;
                #pragma unroll
                for (int q = 0; q < 4; q++) {
                    ulonglong2 v; v.x = accb[2 * q]; v.y = accb[2 * q + 1];
                    r2[q * 128 + rec] = v;
                }
                #pragma unroll
                for (int q = 0; q < 4; q++)
                    rf[(4 + q) * 128 + rec] =
                        make_float4(lg[4 * q], lg[4 * q + 1], lg[4 * q + 2], lg[4 * q + 3]);
            }
            __syncthreads();
            if (kq == 0) {
                #pragma unroll
                for (int rgn = 0; rgn < 3; rgn++) {
                    const char* reg = (rgn == 0) ? dyn : (rgn == 1) ? (dyn + 16384) : (dyn + 65536);
                    const ulonglong2* r2 = (const ulonglong2*)reg;
                    const float4* rf = (const float4*)reg;
                    #pragma unroll
                    for (int q = 0; q < 4; q++) {
                        ulonglong2 v = r2[q * 128 + rec];
                        accb[2 * q]     = add2(accb[2 * q], v.x);
                        accb[2 * q + 1] = add2(accb[2 * q + 1], v.y);
                    }
                    #pragma unroll
                    for (int q = 0; q < 4; q++) {
                        float4 v = rf[(4 + q) * 128 + rec];
                        lg[4 * q] += v.x; lg[4 * q + 1] += v.y;
                        lg[4 * q + 2] += v.z; lg[4 * q + 3] += v.w;
                    }
                }
                float a0[8], a1[8];
                #pragma unroll
                for (int i = 0; i < 4; i++) {
                    float2 q2 = unpack2(accb[i]);
                    a0[2 * i] = q2.x; a0[2 * i + 1] = q2.y;
                    q2 = unpack2(accb[4 + i]);
                    a1[2 * i] = q2.x; a1[2 * i + 1] = q2.y;
                }
                float u0[8], u1[8], mx0 = -1e30f, mx1 = -1e30f;
                #pragma unroll
                for (int k = 0; k < 8; k++) {
                    u0[k] = ftanh(fmaf(a0[k], c0, ba0));
                    u1[k] = ftanh(fmaf(a1[k], c1, ba1));
                    mx0 = fmaxf(mx0, u0[k]);
                    mx1 = fmaxf(mx1, u1[k]);
                }
                float es0 = 0.f, L0 = 0.f, es1 = 0.f, L1 = 0.f;
                #pragma unroll
                for (int k = 0; k < 8; k++) {
                    float e0 = __expf(u0[k] - mx0);
                    float e1 = __expf(u1[k] - mx1);
                    es0 += e0; L0 += e0 * lg[k];
                    es1 += e1; L1 += e1 * lg[8 + k];
                }
                L0 /= es0; L1 /= es1;
                int idx = bB_ * H_DIM + g0;
                float2 fv = __ldcg((const float2*)&g_f[idx]);
                float2 ov = __ldcg((const float2*)&g_o[idx]);
                c0 = fmaf(fv.x, c0, L0);
                c1 = fmaf(fv.y, c1, L1);
                float hn0 = ov.x * ftanh(c0);
                float hn1 = ov.y * ftanh(c1);
                g_hT[g0 * B_DIM + bB_] = hn0;
                g_hT[g1 * B_DIM + bB_] = hn1;
                *(float2*)&out[(size_t)B_DIM * H_DIM + ((size_t)bB_ * T_DIM + t) * H_DIM + g0] =
                    make_float2(hn0, hn1);
                if (t == T_DIM - 1)
                    *(float2*)&out[bB_ * H_DIM + g0] = make_float2(hn0, hn1);
            }
        }

        grid_barrier(2 * t + 2);
    }
#undef PF_A
#undef PF_B
}

// ---------------------------------------------------------------------------
extern "C" void kernel_launch(void* const* d_in, const int* in_sizes, int n_in,
                              void* d_out, int out_size) {
    (void)in_sizes; (void)n_in; (void)out_size;
    Ptrs P;
    for (int i = 0; i < 28; i++) P.p[i] = (const float*)d_in[i];

    cudaFuncSetAttribute(main_kernel,
                         cudaFuncAttributeMaxDynamicSharedMemorySize, DYN_SMEM);

    reset_kernel<<<64, 256>>>();
    main_kernel<<<NBLK, THR, DYN_SMEM>>>(P, (float*)d_out);
}

// round 14
// speedup vs baseline: 1.2650x; 1.0918x over previous
#include <cuda_runtime.h>
#include <cstdint>
#include <cstddef>

#define T_DIM 1024
#define H_DIM 512
#define B_DIM 64
#define NBLK  144
#define THR   512
#define DYN_SMEM 138240

// ---------------------------------------------------------------------------
// Device-global scratch
// ---------------------------------------------------------------------------
__device__ float g_l[B_DIM * H_DIM * 8];        // l[b][h][k]  (k contiguous)
__device__ float g_f[B_DIM * H_DIM];            // f[b][h] (sigmoided)
__device__ float g_o[B_DIM * H_DIM];            // o[b][h] (sigmoided)
__device__ float g_hT[H_DIM * B_DIM];           // hT[h][b]
__device__ volatile unsigned g_flags[NBLK];
__device__ volatile unsigned g_epoch;

// ---------------------------------------------------------------------------
__device__ __forceinline__ unsigned long long pack2(float v) {
    unsigned long long r;
    asm("mov.b64 %0, {%1, %1};" : "=l"(r) : "f"(v));
    return r;
}
__device__ __forceinline__ unsigned long long fma2(unsigned long long a,
                                                   unsigned long long b,
                                                   unsigned long long c) {
    unsigned long long d;
    asm("fma.rn.f32x2 %0, %1, %2, %3;" : "=l"(d) : "l"(a), "l"(b), "l"(c));
    return d;
}
__device__ __forceinline__ unsigned long long add2(unsigned long long a,
                                                   unsigned long long b) {
    unsigned long long d;
    asm("add.rn.f32x2 %0, %1, %2;" : "=l"(d) : "l"(a), "l"(b));
    return d;
}
__device__ __forceinline__ float2 unpack2(unsigned long long v) {
    float2 f;
    asm("mov.b64 {%0, %1}, %2;" : "=f"(f.x), "=f"(f.y) : "l"(v));
    return f;
}

__device__ __forceinline__ void cpa_cg(unsigned dst, const float* src) {
    asm volatile("cp.async.cg.shared.global [%0], [%1], 16;" :: "r"(dst), "l"(src));
}
__device__ __forceinline__ void cpa_ca(unsigned dst, const float* src) {
    asm volatile("cp.async.ca.shared.global [%0], [%1], 16;" :: "r"(dst), "l"(src));
}
#define CP_COMMIT() asm volatile("cp.async.commit_group;" ::: "memory")
#define CP_WAIT1()  asm volatile("cp.async.wait_group 1;" ::: "memory")
#define CP_WAIT0()  asm volatile("cp.async.wait_group 0;" ::: "memory")

__device__ __forceinline__ float fsig(float x) {
    x = fminf(fmaxf(x, -30.f), 30.f);
    return 1.f / (1.f + __expf(-x));
}
__device__ __forceinline__ float ftanh(float x) {
    x = fminf(fmaxf(x, -15.f), 15.f);
    float e = __expf(2.f * x);
    return (e - 1.f) / (e + 1.f);
}

struct Ptrs { const float* p[28]; };

__device__ __forceinline__ void matInfo(const Ptrs& P, int m,
                                        const float*& W, const float*& bias,
                                        const float*& X, int& C) {
    if (m < 4) {
        C = 8; X = P.p[0];
        W = P.p[8 + 3 * m]; bias = P.p[10 + 3 * m];
    } else if (m < 11) {
        int k = m - 4; C = 3;
        X = P.p[(k == 0) ? 1 : 2];                 // aux input gates: x1 then x2 (faithful quirk)
        W = P.p[20] + (size_t)k * 3 * H_DIM; bias = P.p[22] + (size_t)k * H_DIM;
    } else {
        int k = m - 11; C = 3;
        X = P.p[1 + k];                            // aux candidates: x1..x7
        W = P.p[23] + (size_t)k * 3 * H_DIM; bias = P.p[25] + (size_t)k * H_DIM;
    }
}
__device__ __forceinline__ const float* Uptr(const Ptrs& P, int m) {
    if (m < 4)  return P.p[9 + 3 * m];
    if (m < 11) return P.p[21] + (size_t)(m - 4)  * H_DIM * H_DIM;
    return             P.p[24] + (size_t)(m - 11) * H_DIM * H_DIM;
}

// ---------------------------------------------------------------------------
__global__ void reset_kernel() {
    int i = blockIdx.x * blockDim.x + threadIdx.x;
    int n = gridDim.x * blockDim.x;
    if (i == 0) g_epoch = 0u;
    if (i < NBLK) g_flags[i] = 0u;
    for (int k = i; k < H_DIM * B_DIM; k += n) g_hT[k] = 0.f;
}

// ---------------------------------------------------------------------------
__device__ __forceinline__ void grid_barrier(unsigned target) {
    __syncthreads();
    if (threadIdx.x == 0) {
        __threadfence();
        g_flags[blockIdx.x] = target;
    }
    if (blockIdx.x == 0) {
        if (threadIdx.x < NBLK) {
            while (g_flags[threadIdx.x] < target) __nanosleep(64);
        }
        __syncthreads();
        if (threadIdx.x == 0) {
            __threadfence();
            g_epoch = target;
        }
    }
    if (threadIdx.x == 0) {
        while (g_epoch < target) __nanosleep(64);
        __threadfence();
    }
    __syncthreads();
}

// ---------------------------------------------------------------------------
// Persistent kernel: 144 CTAs x 512 threads, 135KB dynamic smem.
// Phase A: z = [h | x | 1] @ [U; W; bias] — input projection folded into the
//   GEMM as 9 extra K-rows (kq3 handles them from persistent smem).
//   cta = p*16 + jt; thread = kq(4) x mt(2) x bq(8) x jp(8): 4j x 8b.
// Phase B (cta<128): cta = bt(8) x gt(16); thread = kq(4) x bloc(8) x gp(16).
// ---------------------------------------------------------------------------
__global__ void __launch_bounds__(THR, 1)
main_kernel(Ptrs P, float* __restrict__ out) {
    extern __shared__ __align__(16) char dyn[];
    // A: sU [2buf][4kq][2mt][32hh][32j] = 64KB @0
    //    sH [2buf][4kq][32hh][64b]      = 64KB @65536
    //    sWext [2mt][9][32]             = 2304B @131072 (persistent)
    //    sXext [2mt][9][64]             = 4608B @133376 (per-step)
    // B: sL [2buf][4kq][32hh][8bl][8k]  = 64KB @0
    //    sW [2buf][4kq][32hh][32g]      = 32KB @65536
    // Exchange: E1 @0, E2 @16384, E3 @65536 (16KB each), mtEx @81920 (8KB)
    float*  sU = (float*)dyn;
    float*  sH = (float*)(dyn + 65536);
    float*  sW = (float*)(dyn + 65536);
    float*  sL = (float*)dyn;
    float*  sWext = (float*)(dyn + 131072);
    float*  sXext = (float*)(dyn + 133376);
    float4* mtEx = (float4*)(dyn + 81920);
    const unsigned smem_u32 = (unsigned)__cvta_generic_to_shared(dyn);

    const int cta = blockIdx.x, tid = threadIdx.x;
    const int kq  = tid >> 7;                 // 0..3
    const int rec = tid & 127;

    // --- phase A ids ---
    const int p   = cta >> 4;
    const int jt  = cta & 15;
    const int jp  = tid & 7;                  // 4 j each
    const int bq  = (tid >> 3) & 7;           // 8 batches each
    const int mt  = (tid >> 6) & 1;
    int m0, m1;
    if      (p == 0) { m0 = 0; m1 = 2; }
    else if (p == 1) { m0 = 1; m1 = 3; }
    else             { m0 = 4 + (p - 2); m1 = 11 + (p - 2); }

    const float *WA, *bA0, *XA; int Ca;
    const float *WB, *bB0, *XB; int Cb;
    matInfo(P, m0, WA, bA0, XA, Ca);
    matInfo(P, m1, WB, bB0, XB, Cb);
    const float* Um[2] = { Uptr(P, m0) + jt * 32, Uptr(P, m1) + jt * 32 };

    // --- phase B ids ---
    const int bt    = cta >> 4;                // cta<128
    const int gt    = cta & 15;
    const int bloc  = (tid >> 4) & 7;
    const int gp    = tid & 15;
    const int bB_   = bt * 8 + bloc;
    const int g0    = gt * 32 + gp * 2;
    const int g1    = g0 + 1;
    const int kq_own = g0 >> 7;
    const int it_own = (g0 >> 5) & 3;
    const int hl0    = g0 & 31;
    const float* W_a = P.p[26];
    const float  ba0 = P.p[27][g0 & (H_DIM - 1)];
    const float  ba1 = P.p[27][g1 & (H_DIM - 1)];
    float c0 = 0.f, c1 = 0.f;

    // Stage persistent W-ext rows (x-projection weights + bias, zero-padded)
    for (int i = tid; i < 576; i += THR) {
        int mts = (i >= 288);
        int r = mts ? i - 288 : i;
        int c = r >> 5, jj = r & 31;
        const float* W = mts ? WB : WA;
        const float* bb = mts ? bB0 : bA0;
        int C = mts ? Cb : Ca;
        float v = (c < C) ? W[(size_t)c * H_DIM + jt * 32 + jj]
                          : (c == 8 ? bb[jt * 32 + jj] : 0.f);
        sWext[mts * 288 + c * 32 + jj] = v;
    }
    __syncthreads();

#define PF_A(it, bufb) do { \
    _Pragma("unroll") \
    for (int r = 0; r < 4; r++) { int i = tid + r * THR; \
        int kqs = i >> 9, mts = (i >> 8) & 1, hhl = (i >> 3) & 31, f4 = i & 7; \
        cpa_ca(smem_u32 + (((((bufb) * 4 + kqs) * 2 + mts) * 256 + hhl * 8 + f4) << 4), \
               Um[mts] + (size_t)(kqs * 128 + (it) * 32 + hhl) * H_DIM + f4 * 4); } \
    _Pragma("unroll") \
    for (int r = 0; r < 4; r++) { int i = tid + r * THR; \
        int kqs = i >> 9, hhl = (i >> 4) & 31, f4 = i & 15; \
        cpa_cg(smem_u32 + 65536 + (((((bufb) * 4 + kqs) * 512) + hhl * 16 + f4) << 4), \
               g_hT + (kqs * 128 + (it) * 32 + hhl) * B_DIM + f4 * 4); } \
    CP_COMMIT(); \
} while (0)
#define PF_B(it, bufb) do { \
    _Pragma("unroll") \
    for (int r = 0; r < 4; r++) { int i = tid + r * THR; \
        int kqs = i >> 9, rr = i & 511, hhl = rr >> 4, bl = (rr >> 1) & 7, k4 = i & 1; \
        cpa_cg(smem_u32 + (((((bufb) * 4 + kqs) * 512) + (hhl * 8 + bl) * 2 + k4) << 4), \
               g_l + ((size_t)(bt * 8 + bl) * H_DIM + kqs * 128 + (it) * 32 + hhl) * 8 + k4 * 4); } \
    _Pragma("unroll") \
    for (int r = 0; r < 2; r++) { int i = tid + r * THR; \
        int kqs = i >> 8, hhl = (i >> 3) & 31, f4 = i & 7; \
        cpa_ca(smem_u32 + 65536 + (((((bufb) * 4 + kqs) * 256) + hhl * 8 + f4) << 4), \
               W_a + (size_t)(kqs * 128 + (it) * 32 + hhl) * H_DIM + gt * 32 + f4 * 4); } \
    CP_COMMIT(); \
} while (0)

    for (int t = 0; t < T_DIM; t++) {
        // =============== Phase A ===============
        unsigned long long acc[16];
        #pragma unroll
        for (int i = 0; i < 16; i++) acc[i] = 0ull;

        PF_A(0, 0);
        PF_A(1, 1);
        // stage x-ext rows (transposed, zero-padded, ones row for bias)
        for (int i = tid; i < 1152; i += THR) {
            int mts = (i >= 576);
            int r = mts ? i - 576 : i;
            int c = r >> 6, b = r & 63;
            const float* X = mts ? XB : XA;
            int C = mts ? Cb : Ca;
            float v = (c < C) ? X[((size_t)b * C + c) * T_DIM + t] : (c == 8 ? 1.f : 0.f);
            sXext[mts * 576 + c * 64 + b] = v;
        }

        #pragma unroll 1
        for (int it = 0; it < 4; it++) {
            if (it == 3) CP_WAIT0(); else CP_WAIT1();
            __syncthreads();
            const int buf = it & 1;
            const float* Uf = sU + ((buf * 4 + kq) * 2 + mt) * 1024;
            const float* Hf = sH + (buf * 4 + kq) * 2048;
            #pragma unroll 4
            for (int hh = 0; hh < 32; hh++) {
                float4 u4 = *(const float4*)(Uf + hh * 32 + jp * 4);
                ulonglong2 hA = *(const ulonglong2*)(Hf + hh * 64 + bq * 8);
                ulonglong2 hB = *(const ulonglong2*)(Hf + hh * 64 + bq * 8 + 4);
                unsigned long long up;
                up = pack2(u4.x);
                acc[0]  = fma2(hA.x, up, acc[0]);  acc[1]  = fma2(hA.y, up, acc[1]);
                acc[2]  = fma2(hB.x, up, acc[2]);  acc[3]  = fma2(hB.y, up, acc[3]);
                up = pack2(u4.y);
                acc[4]  = fma2(hA.x, up, acc[4]);  acc[5]  = fma2(hA.y, up, acc[5]);
                acc[6]  = fma2(hB.x, up, acc[6]);  acc[7]  = fma2(hB.y, up, acc[7]);
                up = pack2(u4.z);
                acc[8]  = fma2(hA.x, up, acc[8]);  acc[9]  = fma2(hA.y, up, acc[9]);
                acc[10] = fma2(hB.x, up, acc[10]); acc[11] = fma2(hB.y, up, acc[11]);
                up = pack2(u4.w);
                acc[12] = fma2(hA.x, up, acc[12]); acc[13] = fma2(hA.y, up, acc[13]);
                acc[14] = fma2(hB.x, up, acc[14]); acc[15] = fma2(hB.y, up, acc[15]);
            }
            if (it == 0) { __syncthreads(); PF_A(2, 0); }
            else if (it == 1) { __syncthreads(); PF_A(3, 1); }
        }

        // kq3: the 9 extra K-rows (x-projection + bias)
        if (kq == 3) {
            const float* We = sWext + mt * 288;
            const float* Xe = sXext + mt * 576;
            #pragma unroll
            for (int c = 0; c < 9; c++) {
                float4 u4 = *(const float4*)(We + c * 32 + jp * 4);
                ulonglong2 hA = *(const ulonglong2*)(Xe + c * 64 + bq * 8);
                ulonglong2 hB = *(const ulonglong2*)(Xe + c * 64 + bq * 8 + 4);
                unsigned long long up;
                up = pack2(u4.x);
                acc[0]  = fma2(hA.x, up, acc[0]);  acc[1]  = fma2(hA.y, up, acc[1]);
                acc[2]  = fma2(hB.x, up, acc[2]);  acc[3]  = fma2(hB.y, up, acc[3]);
                up = pack2(u4.y);
                acc[4]  = fma2(hA.x, up, acc[4]);  acc[5]  = fma2(hA.y, up, acc[5]);
                acc[6]  = fma2(hB.x, up, acc[6]);  acc[7]  = fma2(hB.y, up, acc[7]);
                up = pack2(u4.z);
                acc[8]  = fma2(hA.x, up, acc[8]);  acc[9]  = fma2(hA.y, up, acc[9]);
                acc[10] = fma2(hB.x, up, acc[10]); acc[11] = fma2(hB.y, up, acc[11]);
                up = pack2(u4.w);
                acc[12] = fma2(hA.x, up, acc[12]); acc[13] = fma2(hA.y, up, acc[13]);
                acc[14] = fma2(hB.x, up, acc[14]); acc[15] = fma2(hB.y, up, acc[15]);
            }
        }

        // single-round packed split-K exchange ([slot][rec]: conflict-free)
        if (kq != 0) {
            ulonglong2* reg = (kq == 1) ? (ulonglong2*)dyn
                            : (kq == 2) ? (ulonglong2*)(dyn + 16384)
                                        : (ulonglong2*)(dyn + 65536);
            #pragma unroll
            for (int q = 0; q < 8; q++) {
                ulonglong2 v; v.x = acc[2 * q]; v.y = acc[2 * q + 1];
                reg[q * 128 + rec] = v;
            }
        }
        __syncthreads();
        if (kq == 0) {
            const ulonglong2* R1 = (const ulonglong2*)dyn;
            const ulonglong2* R2 = (const ulonglong2*)(dyn + 16384);
            const ulonglong2* R3 = (const ulonglong2*)(dyn + 65536);
            float z[32];
            #pragma unroll
            for (int q = 0; q < 8; q++) {
                ulonglong2 v1 = R1[q * 128 + rec];
                ulonglong2 v2 = R2[q * 128 + rec];
                ulonglong2 v3 = R3[q * 128 + rec];
                unsigned long long s0 = add2(add2(acc[2 * q], v1.x), add2(v2.x, v3.x));
                unsigned long long s1 = add2(add2(acc[2 * q + 1], v1.y), add2(v2.y, v3.y));
                float2 q2 = unpack2(s0);
                z[4 * q] = q2.x; z[4 * q + 1] = q2.y;
                q2 = unpack2(s1);
                z[4 * q + 2] = q2.x; z[4 * q + 3] = q2.y;
            }
            if (p == 1) {
                float* dst = mt ? g_o : g_f;
                #pragma unroll
                for (int jj = 0; jj < 4; jj++)
                    #pragma unroll
                    for (int b8 = 0; b8 < 8; b8++)
                        dst[(bq * 8 + b8) * H_DIM + jt * 32 + jp * 4 + jj] =
                            fsig(z[(jj * 4 + (b8 >> 1)) * 2 + (b8 & 1)]);
            } else if (mt == 1) {
                int idx = bq * 8 + jp;
                #pragma unroll
                for (int q4 = 0; q4 < 8; q4++)
                    mtEx[q4 * 64 + idx] =
                        make_float4(z[4 * q4], z[4 * q4 + 1], z[4 * q4 + 2], z[4 * q4 + 3]);
            }
            __syncthreads();
            if (mt == 0 && p != 1) {
                int idx = bq * 8 + jp;
                float zc[32];
                #pragma unroll
                for (int q4 = 0; q4 < 8; q4++) {
                    float4 v = mtEx[q4 * 64 + idx];
                    zc[4 * q4] = v.x; zc[4 * q4 + 1] = v.y;
                    zc[4 * q4 + 2] = v.z; zc[4 * q4 + 3] = v.w;
                }
                int k = (p == 0) ? 0 : (p - 1);
                #pragma unroll
                for (int jj = 0; jj < 4; jj++)
                    #pragma unroll
                    for (int b8 = 0; b8 < 8; b8++) {
                        int idz = (jj * 4 + (b8 >> 1)) * 2 + (b8 & 1);
                        g_l[((size_t)(bq * 8 + b8) * H_DIM + jt * 32 + jp * 4 + jj) * 8 + k] =
                            fsig(z[idz]) * ftanh(zc[idz]);
                    }
            }
        } else {
            __syncthreads();
        }

        grid_barrier(2 * t + 1);

        // =============== Phase B ===============
        if (cta < 128) {
            unsigned long long accb[8];
            #pragma unroll
            for (int i = 0; i < 8; i++) accb[i] = 0ull;
            float lg[16];
            #pragma unroll
            for (int i = 0; i < 16; i++) lg[i] = 0.f;

            PF_B(0, 0);
            PF_B(1, 1);

            #pragma unroll 1
            for (int it = 0; it < 4; it++) {
                if (it == 3) CP_WAIT0(); else CP_WAIT1();
                __syncthreads();
                const int buf = it & 1;
                const float* Wf = sW + (buf * 4 + kq) * 1024;
                const float* Lf = sL + (buf * 4 + kq) * 2048;
                if (kq == kq_own && it == it_own) {
                    const ulonglong2* Lv = (const ulonglong2*)Lf;
                    ulonglong2 v0 = Lv[hl0 * 16 + bloc * 2];
                    ulonglong2 v1 = Lv[hl0 * 16 + bloc * 2 + 1];
                    ulonglong2 v2 = Lv[(hl0 + 1) * 16 + bloc * 2];
                    ulonglong2 v3 = Lv[(hl0 + 1) * 16 + bloc * 2 + 1];
                    float2 q2;
                    q2 = unpack2(v0.x); lg[0] = q2.x; lg[1] = q2.y;
                    q2 = unpack2(v0.y); lg[2] = q2.x; lg[3] = q2.y;
                    q2 = unpack2(v1.x); lg[4] = q2.x; lg[5] = q2.y;
                    q2 = unpack2(v1.y); lg[6] = q2.x; lg[7] = q2.y;
                    q2 = unpack2(v2.x); lg[8] = q2.x; lg[9] = q2.y;
                    q2 = unpack2(v2.y); lg[10] = q2.x; lg[11] = q2.y;
                    q2 = unpack2(v3.x); lg[12] = q2.x; lg[13] = q2.y;
                    q2 = unpack2(v3.y); lg[14] = q2.x; lg[15] = q2.y;
                }
                #pragma unroll 4
                for (int hh = 0; hh < 32; hh++) {
                    float2 wv = *(const float2*)(Wf + hh * 32 + gp * 2);
                    const ulonglong2* Lv = (const ulonglong2*)Lf;
                    ulonglong2 v0 = Lv[hh * 16 + bloc * 2];
                    ulonglong2 v1 = Lv[hh * 16 + bloc * 2 + 1];
                    unsigned long long w0 = pack2(wv.x);
                    unsigned long long w1 = pack2(wv.y);
                    accb[0] = fma2(v0.x, w0, accb[0]);
                    accb[1] = fma2(v0.y, w0, accb[1]);
                    accb[2] = fma2(v1.x, w0, accb[2]);
                    accb[3] = fma2(v1.y, w0, accb[3]);
                    accb[4] = fma2(v0.x, w1, accb[4]);
                    accb[5] = fma2(v0.y, w1, accb[5]);
                    accb[6] = fma2(v1.x, w1, accb[6]);
                    accb[7] = fma2(v1.y, w1, accb[7]);
                }
                if (it == 0) { __syncthreads(); PF_B(2, 0); }
                else if (it == 1) { __syncthreads(); PF_B(3, 1); }
            }

            // single-round packed exchange (a via add2; lg sum-merges, zero-init)
            if (kq != 0) {
                char* reg = (kq == 1) ? dyn : (kq == 2) ? (dyn + 16384) : (dyn + 65536);
                ulonglong2* r2 = (ulonglong2*)reg;
                float4* rf = (float4*)reg;
                #pragma unroll
                for (int q = 0; q < 4; q++) {
                    ulonglong2 v; v.x = accb[2 * q]; v.y = accb[2 * q + 1];
                    r2[q * 128 + rec] = v;
                }
                #pragma unroll
                for (int q = 0; q < 4; q++)
                    rf[(4 + q) * 128 + rec] =
                        make_float4(lg[4 * q], lg[4 * q + 1], lg[4 * q + 2], lg[4 * q + 3]);
            }
            __syncthreads();
            if (kq == 0) {
                #pragma unroll
                for (int rgn = 0; rgn < 3; rgn++) {
                    const char* reg = (rgn == 0) ? dyn : (rgn == 1) ? (dyn + 16384) : (dyn + 65536);
                    const ulonglong2* r2 = (const ulonglong2*)reg;
                    const float4* rf = (const float4*)reg;
                    #pragma unroll
                    for (int q = 0; q < 4; q++) {
                        ulonglong2 v = r2[q * 128 + rec];
                        accb[2 * q]     = add2(accb[2 * q], v.x);
                        accb[2 * q + 1] = add2(accb[2 * q + 1], v.y);
                    }
                    #pragma unroll
                    for (int q = 0; q < 4; q++) {
                        float4 v = rf[(4 + q) * 128 + rec];
                        lg[4 * q] += v.x; lg[4 * q + 1] += v.y;
                        lg[4 * q + 2] += v.z; lg[4 * q + 3] += v.w;
                    }
                }
                float a0[8], a1[8];
                #pragma unroll
                for (int i = 0; i < 4; i++) {
                    float2 q2 = unpack2(accb[i]);
                    a0[2 * i] = q2.x; a0[2 * i + 1] = q2.y;
                    q2 = unpack2(accb[4 + i]);
                    a1[2 * i] = q2.x; a1[2 * i + 1] = q2.y;
                }
                float u0[8], u1[8], mx0 = -1e30f, mx1 = -1e30f;
                #pragma unroll
                for (int k = 0; k < 8; k++) {
                    u0[k] = ftanh(fmaf(a0[k], c0, ba0));
                    u1[k] = ftanh(fmaf(a1[k], c1, ba1));
                    mx0 = fmaxf(mx0, u0[k]);
                    mx1 = fmaxf(mx1, u1[k]);
                }
                float es0 = 0.f, L0 = 0.f, es1 = 0.f, L1 = 0.f;
                #pragma unroll
                for (int k = 0; k < 8; k++) {
                    float e0 = __expf(u0[k] - mx0);
                    float e1 = __expf(u1[k] - mx1);
                    es0 += e0; L0 += e0 * lg[k];
                    es1 += e1; L1 += e1 * lg[8 + k];
                }
                L0 /= es0; L1 /= es1;
                int idx = bB_ * H_DIM + g0;
                float2 fv = __ldcg((const float2*)&g_f[idx]);
                float2 ov = __ldcg((const float2*)&g_o[idx]);
                c0 = fmaf(fv.x, c0, L0);
                c1 = fmaf(fv.y, c1, L1);
                float hn0 = ov.x * ftanh(c0);
                float hn1 = ov.y * ftanh(c1);
                g_hT[g0 * B_DIM + bB_] = hn0;
                g_hT[g1 * B_DIM + bB_] = hn1;
                *(float2*)&out[(size_t)B_DIM * H_DIM + ((size_t)bB_ * T_DIM + t) * H_DIM + g0] =
                    make_float2(hn0, hn1);
                if (t == T_DIM - 1)
                    *(float2*)&out[bB_ * H_DIM + g0] = make_float2(hn0, hn1);
            }
        }

        grid_barrier(2 * t + 2);
    }
#undef PF_A
#undef PF_B
}

// ---------------------------------------------------------------------------
extern "C" void kernel_launch(void* const* d_in, const int* in_sizes, int n_in,
                              void* d_out, int out_size) {
    (void)in_sizes; (void)n_in; (void)out_size;
    Ptrs P;
    for (int i = 0; i < 28; i++) P.p[i] = (const float*)d_in[i];

    cudaFuncSetAttribute(main_kernel,
                         cudaFuncAttributeMaxDynamicSharedMemorySize, DYN_SMEM);

    reset_kernel<<<64, 256>>>();
    main_kernel<<<NBLK, THR, DYN_SMEM>>>(P, (float*)d_out);
}